// round 6
// baseline (speedup 1.0000x reference)
#include <cuda_runtime.h>
#include <cstdint>

#define EMB 128
#define MAX_USERS 65536
#define MAX_GROUPS 4096

// scratch (allocation-free rule: __device__ globals)
__device__ float g_per_user[(size_t)MAX_USERS * EMB];   // 32 MB, kept L2-resident
__device__ int   g_u_off[MAX_USERS + 1];
__device__ int   g_g_off[MAX_GROUPS + 1];

__device__ __forceinline__ int lower_bound_i32(const int* __restrict__ a, int n, int key) {
    int lo = 0, hi = n;
    while (lo < hi) {
        int m = (lo + hi) >> 1;
        if (__ldg(a + m) < key) lo = m + 1; else hi = m;
    }
    return lo;
}

// Merged prologue: fill both offset arrays with thread-parallel binary searches.
__global__ void __launch_bounds__(256) offsets_kernel(
    const int* __restrict__ buid, const int* __restrict__ ugid,
    int n_beh, int n_users, int num_groups)
{
    int i = blockIdx.x * blockDim.x + threadIdx.x;
    if (i <= n_users) g_u_off[i] = lower_bound_i32(buid, n_beh, i);
    int gi = i - (n_users + 1);
    if (gi >= 0 && gi <= num_groups) g_g_off[gi] = lower_bound_i32(ugid, n_users, gi);
}

// ---------------------------------------------------------------------------
// Kernel 1: one warp per user. Offsets precomputed. Unroll x4, 2 accumulators.
// Scratch stored with default policy so it remains L2-resident for kernel 2.
// ---------------------------------------------------------------------------
__global__ void __launch_bounds__(256) per_user_kernel(
    const int* __restrict__ user_ids,
    const int* __restrict__ bitem,
    const float* __restrict__ bcnt,
    const float* __restrict__ user_table,
    const float* __restrict__ item_table,
    int n_users)
{
    const int warp = (blockIdx.x * blockDim.x + threadIdx.x) >> 5;
    const int lane = threadIdx.x & 31;
    if (warp >= n_users) return;
    const int u   = warp;
    const int col = lane * 4;

    float4* dst = reinterpret_cast<float4*>(g_per_user + (size_t)u * EMB + col);

    const int uid = __ldg(user_ids + u);
    if (uid == 0) {
        *dst = make_float4(0.f, 0.f, 0.f, 0.f);
        return;
    }

    const int s = g_u_off[u];
    const int e = g_u_off[u + 1];

    float4 a0 = make_float4(0.f, 0.f, 0.f, 0.f);
    float4 a1 = make_float4(0.f, 0.f, 0.f, 0.f);

    int j = s;
    for (; j + 3 < e; j += 4) {
        int   i0 = __ldcs(bitem + j + 0);
        int   i1 = __ldcs(bitem + j + 1);
        int   i2 = __ldcs(bitem + j + 2);
        int   i3 = __ldcs(bitem + j + 3);
        float c0 = __ldcs(bcnt + j + 0);
        float c1 = __ldcs(bcnt + j + 1);
        float c2 = __ldcs(bcnt + j + 2);
        float c3 = __ldcs(bcnt + j + 3);
        float4 v0 = *reinterpret_cast<const float4*>(item_table + (size_t)i0 * EMB + col);
        float4 v1 = *reinterpret_cast<const float4*>(item_table + (size_t)i1 * EMB + col);
        float4 v2 = *reinterpret_cast<const float4*>(item_table + (size_t)i2 * EMB + col);
        float4 v3 = *reinterpret_cast<const float4*>(item_table + (size_t)i3 * EMB + col);
        a0.x += c0 * v0.x; a0.y += c0 * v0.y; a0.z += c0 * v0.z; a0.w += c0 * v0.w;
        a1.x += c1 * v1.x; a1.y += c1 * v1.y; a1.z += c1 * v1.z; a1.w += c1 * v1.w;
        a0.x += c2 * v2.x; a0.y += c2 * v2.y; a0.z += c2 * v2.z; a0.w += c2 * v2.w;
        a1.x += c3 * v3.x; a1.y += c3 * v3.y; a1.z += c3 * v3.z; a1.w += c3 * v3.w;
    }
    for (; j < e; j++) {
        int   i0 = __ldcs(bitem + j);
        float c0 = __ldcs(bcnt + j);
        float4 v0 = *reinterpret_cast<const float4*>(item_table + (size_t)i0 * EMB + col);
        a0.x += c0 * v0.x; a0.y += c0 * v0.y; a0.z += c0 * v0.z; a0.w += c0 * v0.w;
    }

    float4 ue = *reinterpret_cast<const float4*>(user_table + (size_t)uid * EMB + col);
    float4 outv;
    outv.x = (a0.x + a1.x) * ue.x;
    outv.y = (a0.y + a1.y) * ue.y;
    outv.z = (a0.z + a1.z) * ue.z;
    outv.w = (a0.w + a1.w) * ue.w;
    *dst = outv;
}

// ---------------------------------------------------------------------------
// Kernel 2: one 128-thread CTA per group. 32 lanes own float4 column slices,
// 4 user-partitions in parallel (stride 4), fixed-order smem combine.
// Scratch is L2-resident -> L2-latency reads.
// ---------------------------------------------------------------------------
__global__ void __launch_bounds__(128) group_sum_kernel(
    float* __restrict__ out, int num_groups)
{
    const int g    = blockIdx.x;
    const int lane = threadIdx.x & 31;
    const int part = threadIdx.x >> 5;   // 0..3
    const int col  = lane * 4;

    __shared__ float4 s_part[4][32];

    const int s = g_g_off[g];
    const int e = g_g_off[g + 1];

    float4 acc = make_float4(0.f, 0.f, 0.f, 0.f);
    for (int u = s + part; u < e; u += 4) {
        float4 v = *reinterpret_cast<const float4*>(g_per_user + (size_t)u * EMB + col);
        acc.x += v.x; acc.y += v.y; acc.z += v.z; acc.w += v.w;
    }
    s_part[part][lane] = acc;
    __syncthreads();

    if (part == 0) {
        float4 r0 = s_part[0][lane];
        float4 r1 = s_part[1][lane];
        float4 r2 = s_part[2][lane];
        float4 r3 = s_part[3][lane];
        float4 r;
        r.x = (r0.x + r1.x) + (r2.x + r3.x);
        r.y = (r0.y + r1.y) + (r2.y + r3.y);
        r.z = (r0.z + r1.z) + (r2.z + r3.z);
        r.w = (r0.w + r1.w) + (r2.w + r3.w);
        *reinterpret_cast<float4*>(out + (size_t)g * EMB + col) = r;
    }
}

extern "C" void kernel_launch(void* const* d_in, const int* in_sizes, int n_in,
                              void* d_out, int out_size)
{
    const int*   user_ids   = (const int*)  d_in[0];
    const int*   ugid       = (const int*)  d_in[1];
    const int*   bitem      = (const int*)  d_in[2];
    const float* bcnt       = (const float*)d_in[3];
    const int*   buid       = (const int*)  d_in[4];
    const float* user_table = (const float*)d_in[5];
    const float* item_table = (const float*)d_in[6];

    const int n_users    = in_sizes[0];
    const int n_beh      = in_sizes[2];
    const int num_groups = out_size / EMB;

    float* out = (float*)d_out;

    {
        int total = (n_users + 1) + (num_groups + 1);
        offsets_kernel<<<(total + 255) / 256, 256>>>(buid, ugid, n_beh, n_users, num_groups);
    }

    {
        const int warps_per_block = 8;
        const int threads = warps_per_block * 32;
        const int blocks = (n_users + warps_per_block - 1) / warps_per_block;
        per_user_kernel<<<blocks, threads>>>(user_ids, bitem, bcnt,
                                             user_table, item_table, n_users);
    }

    group_sum_kernel<<<num_groups, 128>>>(out, num_groups);
}

// round 7
// speedup vs baseline: 1.0191x; 1.0191x over previous
#include <cuda_runtime.h>
#include <cstdint>

#define EMB 128
#define MAX_USERS 65536
#define MAX_GROUPS 4096

// scratch (allocation-free rule: __device__ globals)
__device__ float g_per_user[(size_t)MAX_USERS * EMB];   // 32 MB, kept L2-resident
__device__ int   g_u_off[MAX_USERS + 1];
__device__ int   g_g_off[MAX_GROUPS + 1];

// ---------------------------------------------------------------------------
// Prologue: O(n) adjacency scatter over both sorted key arrays.
//   u_off[u] = lower_bound(buid, u)   for u in [0, n_users]
//   g_off[g] = lower_bound(ugid, g)   for g in [0, num_groups]
// One thread per element; boundary threads fill the key gaps. Coalesced
// streaming reads, no dependent-load chains.
// ---------------------------------------------------------------------------
__global__ void __launch_bounds__(256) offsets_scatter_kernel(
    const int* __restrict__ buid, const int* __restrict__ ugid,
    int n_beh, int n_users, int num_groups)
{
    int i = blockIdx.x * blockDim.x + threadIdx.x;

    if (i < n_beh) {
        int cur  = buid[i];
        int prev = (i == 0) ? -1 : buid[i - 1];
        for (int u = prev + 1; u <= cur; u++) g_u_off[u] = i;
        if (i == n_beh - 1) {
            for (int u = cur + 1; u <= n_users; u++) g_u_off[u] = n_beh;
        }
        return;
    }

    int k = i - n_beh;
    if (k < n_users) {
        int cur  = ugid[k];
        int prev = (k == 0) ? -1 : ugid[k - 1];
        for (int g = prev + 1; g <= cur; g++) g_g_off[g] = k;
        if (k == n_users - 1) {
            for (int g = cur + 1; g <= num_groups; g++) g_g_off[g] = n_users;
        }
    }
}

// ---------------------------------------------------------------------------
// Kernel 1: one warp per user. Offsets precomputed. Unroll x4, 2 accumulators.
// Scratch stored with default policy so it remains L2-resident for kernel 2.
// ---------------------------------------------------------------------------
__global__ void __launch_bounds__(256) per_user_kernel(
    const int* __restrict__ user_ids,
    const int* __restrict__ bitem,
    const float* __restrict__ bcnt,
    const float* __restrict__ user_table,
    const float* __restrict__ item_table,
    int n_users)
{
    const int warp = (blockIdx.x * blockDim.x + threadIdx.x) >> 5;
    const int lane = threadIdx.x & 31;
    if (warp >= n_users) return;
    const int u   = warp;
    const int col = lane * 4;

    float4* dst = reinterpret_cast<float4*>(g_per_user + (size_t)u * EMB + col);

    const int uid = __ldg(user_ids + u);
    if (uid == 0) {
        *dst = make_float4(0.f, 0.f, 0.f, 0.f);
        return;
    }

    const int s = g_u_off[u];
    const int e = g_u_off[u + 1];

    float4 a0 = make_float4(0.f, 0.f, 0.f, 0.f);
    float4 a1 = make_float4(0.f, 0.f, 0.f, 0.f);

    int j = s;
    for (; j + 3 < e; j += 4) {
        int   i0 = __ldcs(bitem + j + 0);
        int   i1 = __ldcs(bitem + j + 1);
        int   i2 = __ldcs(bitem + j + 2);
        int   i3 = __ldcs(bitem + j + 3);
        float c0 = __ldcs(bcnt + j + 0);
        float c1 = __ldcs(bcnt + j + 1);
        float c2 = __ldcs(bcnt + j + 2);
        float c3 = __ldcs(bcnt + j + 3);
        float4 v0 = *reinterpret_cast<const float4*>(item_table + (size_t)i0 * EMB + col);
        float4 v1 = *reinterpret_cast<const float4*>(item_table + (size_t)i1 * EMB + col);
        float4 v2 = *reinterpret_cast<const float4*>(item_table + (size_t)i2 * EMB + col);
        float4 v3 = *reinterpret_cast<const float4*>(item_table + (size_t)i3 * EMB + col);
        a0.x += c0 * v0.x; a0.y += c0 * v0.y; a0.z += c0 * v0.z; a0.w += c0 * v0.w;
        a1.x += c1 * v1.x; a1.y += c1 * v1.y; a1.z += c1 * v1.z; a1.w += c1 * v1.w;
        a0.x += c2 * v2.x; a0.y += c2 * v2.y; a0.z += c2 * v2.z; a0.w += c2 * v2.w;
        a1.x += c3 * v3.x; a1.y += c3 * v3.y; a1.z += c3 * v3.z; a1.w += c3 * v3.w;
    }
    for (; j < e; j++) {
        int   i0 = __ldcs(bitem + j);
        float c0 = __ldcs(bcnt + j);
        float4 v0 = *reinterpret_cast<const float4*>(item_table + (size_t)i0 * EMB + col);
        a0.x += c0 * v0.x; a0.y += c0 * v0.y; a0.z += c0 * v0.z; a0.w += c0 * v0.w;
    }

    float4 ue = *reinterpret_cast<const float4*>(user_table + (size_t)uid * EMB + col);
    float4 outv;
    outv.x = (a0.x + a1.x) * ue.x;
    outv.y = (a0.y + a1.y) * ue.y;
    outv.z = (a0.z + a1.z) * ue.z;
    outv.w = (a0.w + a1.w) * ue.w;
    *dst = outv;
}

// ---------------------------------------------------------------------------
// Kernel 2: one 128-thread CTA per group. 32 lanes own float4 column slices,
// 4 user-partitions in parallel (stride 4), fixed-order smem combine.
// Scratch is L2-resident -> L2-latency reads.
// ---------------------------------------------------------------------------
__global__ void __launch_bounds__(128) group_sum_kernel(
    float* __restrict__ out, int num_groups)
{
    const int g    = blockIdx.x;
    const int lane = threadIdx.x & 31;
    const int part = threadIdx.x >> 5;   // 0..3
    const int col  = lane * 4;

    __shared__ float4 s_part[4][32];

    const int s = g_g_off[g];
    const int e = g_g_off[g + 1];

    float4 acc = make_float4(0.f, 0.f, 0.f, 0.f);
    for (int u = s + part; u < e; u += 4) {
        float4 v = *reinterpret_cast<const float4*>(g_per_user + (size_t)u * EMB + col);
        acc.x += v.x; acc.y += v.y; acc.z += v.z; acc.w += v.w;
    }
    s_part[part][lane] = acc;
    __syncthreads();

    if (part == 0) {
        float4 r0 = s_part[0][lane];
        float4 r1 = s_part[1][lane];
        float4 r2 = s_part[2][lane];
        float4 r3 = s_part[3][lane];
        float4 r;
        r.x = (r0.x + r1.x) + (r2.x + r3.x);
        r.y = (r0.y + r1.y) + (r2.y + r3.y);
        r.z = (r0.z + r1.z) + (r2.z + r3.z);
        r.w = (r0.w + r1.w) + (r2.w + r3.w);
        *reinterpret_cast<float4*>(out + (size_t)g * EMB + col) = r;
    }
}

extern "C" void kernel_launch(void* const* d_in, const int* in_sizes, int n_in,
                              void* d_out, int out_size)
{
    const int*   user_ids   = (const int*)  d_in[0];
    const int*   ugid       = (const int*)  d_in[1];
    const int*   bitem      = (const int*)  d_in[2];
    const float* bcnt       = (const float*)d_in[3];
    const int*   buid       = (const int*)  d_in[4];
    const float* user_table = (const float*)d_in[5];
    const float* item_table = (const float*)d_in[6];

    const int n_users    = in_sizes[0];
    const int n_beh      = in_sizes[2];
    const int num_groups = out_size / EMB;

    float* out = (float*)d_out;

    {
        int total = n_beh + n_users;
        offsets_scatter_kernel<<<(total + 255) / 256, 256>>>(
            buid, ugid, n_beh, n_users, num_groups);
    }

    {
        const int warps_per_block = 8;
        const int threads = warps_per_block * 32;
        const int blocks = (n_users + warps_per_block - 1) / warps_per_block;
        per_user_kernel<<<blocks, threads>>>(user_ids, bitem, bcnt,
                                             user_table, item_table, n_users);
    }

    group_sum_kernel<<<num_groups, 128>>>(out, num_groups);
}

// round 8
// speedup vs baseline: 1.0700x; 1.0500x over previous
#include <cuda_runtime.h>
#include <cstdint>

#define EMB 128
#define MAX_USERS 65536
#define MAX_GROUPS 4096

// scratch (allocation-free rule: __device__ globals)
__device__ float g_per_user[(size_t)MAX_USERS * EMB];   // 32 MB, kept L2-resident
__device__ int   g_u_off[MAX_USERS + 1];
__device__ int   g_g_off[MAX_GROUPS + 1];

// ---------------------------------------------------------------------------
// Prologue: O(n) adjacency scatter, vectorized 4x.
//   u_off[u] = lower_bound(buid, u),  g_off[g] = lower_bound(ugid, g)
// Each thread owns 4 consecutive keys (one int4 load) plus the scalar
// predecessor, and writes offsets at key boundaries. Coalesced, no chains.
// ---------------------------------------------------------------------------
__device__ __forceinline__ void scatter4(const int* __restrict__ keys, int n,
                                         int* __restrict__ off, int max_key,
                                         int slot)
{
    const int base = slot * 4;
    if (base >= n) return;

    if (base + 4 <= n) {
        int4 v = *reinterpret_cast<const int4*>(keys + base);
        int prev = (base == 0) ? -1 : __ldg(keys + base - 1);
        int k0 = v.x, k1 = v.y, k2 = v.z, k3 = v.w;
        for (int u = prev + 1; u <= k0; u++) off[u] = base + 0;
        for (int u = k0  + 1; u <= k1; u++) off[u] = base + 1;
        for (int u = k1  + 1; u <= k2; u++) off[u] = base + 2;
        for (int u = k2  + 1; u <= k3; u++) off[u] = base + 3;
        if (base + 4 == n) {
            for (int u = k3 + 1; u <= max_key; u++) off[u] = n;
        }
    } else {
        // tail (only if n % 4 != 0)
        int prev = (base == 0) ? -1 : __ldg(keys + base - 1);
        for (int j = base; j < n; j++) {
            int cur = __ldg(keys + j);
            for (int u = prev + 1; u <= cur; u++) off[u] = j;
            prev = cur;
        }
        for (int u = prev + 1; u <= max_key; u++) off[u] = n;
    }
}

__global__ void __launch_bounds__(256) offsets_scatter_kernel(
    const int* __restrict__ buid, const int* __restrict__ ugid,
    int n_beh, int n_users, int num_groups)
{
    const int i = blockIdx.x * blockDim.x + threadIdx.x;
    const int n_beh_slots = (n_beh + 3) >> 2;

    if (i < n_beh_slots) {
        scatter4(buid, n_beh, g_u_off, n_users, i);
    } else {
        scatter4(ugid, n_users, g_g_off, num_groups, i - n_beh_slots);
    }
}

// ---------------------------------------------------------------------------
// Kernel 1: one warp per user. Offsets precomputed. Unroll x4, 2 accumulators.
// Scratch stored with default policy so it remains L2-resident for kernel 2.
// ---------------------------------------------------------------------------
__global__ void __launch_bounds__(256) per_user_kernel(
    const int* __restrict__ user_ids,
    const int* __restrict__ bitem,
    const float* __restrict__ bcnt,
    const float* __restrict__ user_table,
    const float* __restrict__ item_table,
    int n_users)
{
    const int warp = (blockIdx.x * blockDim.x + threadIdx.x) >> 5;
    const int lane = threadIdx.x & 31;
    if (warp >= n_users) return;
    const int u   = warp;
    const int col = lane * 4;

    float4* dst = reinterpret_cast<float4*>(g_per_user + (size_t)u * EMB + col);

    const int uid = __ldg(user_ids + u);
    if (uid == 0) {
        *dst = make_float4(0.f, 0.f, 0.f, 0.f);
        return;
    }

    const int s = g_u_off[u];
    const int e = g_u_off[u + 1];

    float4 a0 = make_float4(0.f, 0.f, 0.f, 0.f);
    float4 a1 = make_float4(0.f, 0.f, 0.f, 0.f);

    int j = s;
    for (; j + 3 < e; j += 4) {
        int   i0 = __ldcs(bitem + j + 0);
        int   i1 = __ldcs(bitem + j + 1);
        int   i2 = __ldcs(bitem + j + 2);
        int   i3 = __ldcs(bitem + j + 3);
        float c0 = __ldcs(bcnt + j + 0);
        float c1 = __ldcs(bcnt + j + 1);
        float c2 = __ldcs(bcnt + j + 2);
        float c3 = __ldcs(bcnt + j + 3);
        float4 v0 = *reinterpret_cast<const float4*>(item_table + (size_t)i0 * EMB + col);
        float4 v1 = *reinterpret_cast<const float4*>(item_table + (size_t)i1 * EMB + col);
        float4 v2 = *reinterpret_cast<const float4*>(item_table + (size_t)i2 * EMB + col);
        float4 v3 = *reinterpret_cast<const float4*>(item_table + (size_t)i3 * EMB + col);
        a0.x += c0 * v0.x; a0.y += c0 * v0.y; a0.z += c0 * v0.z; a0.w += c0 * v0.w;
        a1.x += c1 * v1.x; a1.y += c1 * v1.y; a1.z += c1 * v1.z; a1.w += c1 * v1.w;
        a0.x += c2 * v2.x; a0.y += c2 * v2.y; a0.z += c2 * v2.z; a0.w += c2 * v2.w;
        a1.x += c3 * v3.x; a1.y += c3 * v3.y; a1.z += c3 * v3.z; a1.w += c3 * v3.w;
    }
    for (; j < e; j++) {
        int   i0 = __ldcs(bitem + j);
        float c0 = __ldcs(bcnt + j);
        float4 v0 = *reinterpret_cast<const float4*>(item_table + (size_t)i0 * EMB + col);
        a0.x += c0 * v0.x; a0.y += c0 * v0.y; a0.z += c0 * v0.z; a0.w += c0 * v0.w;
    }

    float4 ue = *reinterpret_cast<const float4*>(user_table + (size_t)uid * EMB + col);
    float4 outv;
    outv.x = (a0.x + a1.x) * ue.x;
    outv.y = (a0.y + a1.y) * ue.y;
    outv.z = (a0.z + a1.z) * ue.z;
    outv.w = (a0.w + a1.w) * ue.w;
    *dst = outv;
}

// ---------------------------------------------------------------------------
// Kernel 2: one 128-thread CTA per group. 32 lanes own float4 column slices,
// 4 user-partitions in parallel (stride 4), fixed-order smem combine.
// Scratch is L2-resident -> L2-latency reads.
// ---------------------------------------------------------------------------
__global__ void __launch_bounds__(128) group_sum_kernel(
    float* __restrict__ out, int num_groups)
{
    const int g    = blockIdx.x;
    const int lane = threadIdx.x & 31;
    const int part = threadIdx.x >> 5;   // 0..3
    const int col  = lane * 4;

    __shared__ float4 s_part[4][32];

    const int s = g_g_off[g];
    const int e = g_g_off[g + 1];

    float4 acc = make_float4(0.f, 0.f, 0.f, 0.f);
    for (int u = s + part; u < e; u += 4) {
        float4 v = *reinterpret_cast<const float4*>(g_per_user + (size_t)u * EMB + col);
        acc.x += v.x; acc.y += v.y; acc.z += v.z; acc.w += v.w;
    }
    s_part[part][lane] = acc;
    __syncthreads();

    if (part == 0) {
        float4 r0 = s_part[0][lane];
        float4 r1 = s_part[1][lane];
        float4 r2 = s_part[2][lane];
        float4 r3 = s_part[3][lane];
        float4 r;
        r.x = (r0.x + r1.x) + (r2.x + r3.x);
        r.y = (r0.y + r1.y) + (r2.y + r3.y);
        r.z = (r0.z + r1.z) + (r2.z + r3.z);
        r.w = (r0.w + r1.w) + (r2.w + r3.w);
        *reinterpret_cast<float4*>(out + (size_t)g * EMB + col) = r;
    }
}

extern "C" void kernel_launch(void* const* d_in, const int* in_sizes, int n_in,
                              void* d_out, int out_size)
{
    const int*   user_ids   = (const int*)  d_in[0];
    const int*   ugid       = (const int*)  d_in[1];
    const int*   bitem      = (const int*)  d_in[2];
    const float* bcnt       = (const float*)d_in[3];
    const int*   buid       = (const int*)  d_in[4];
    const float* user_table = (const float*)d_in[5];
    const float* item_table = (const float*)d_in[6];

    const int n_users    = in_sizes[0];
    const int n_beh      = in_sizes[2];
    const int num_groups = out_size / EMB;

    float* out = (float*)d_out;

    {
        int slots = ((n_beh + 3) >> 2) + ((n_users + 3) >> 2);
        offsets_scatter_kernel<<<(slots + 255) / 256, 256>>>(
            buid, ugid, n_beh, n_users, num_groups);
    }

    {
        const int warps_per_block = 8;
        const int threads = warps_per_block * 32;
        const int blocks = (n_users + warps_per_block - 1) / warps_per_block;
        per_user_kernel<<<blocks, threads>>>(user_ids, bitem, bcnt,
                                             user_table, item_table, n_users);
    }

    group_sum_kernel<<<num_groups, 128>>>(out, num_groups);
}